// round 13
// baseline (speedup 1.0000x reference)
#include <cuda_runtime.h>
#include <cuda_fp16.h>
#include <cstdint>

#define T_STEPS 1024
#define A_DIM   64
#define H_DIM   2048
#define H3      (3 * H_DIM)
#define NBLK    128
#define NTHR    1024           // 32 warps: split-K, 2 warps per output element
#define JPB     16             // outputs per CTA
// sv(fp32 8KB) + fc1 + fc2 (half, 64KB each) + partials (3*32 fp32)
#define SMEM_BYTES (8192 + 2 * JPB * H_DIM * 2 + 384)

// ---------------- scratch (static device allocs: allowed) ----------------
__device__ float  g_GI[(size_t)T_STEPS * H3];       // 25.2 MB
__device__ float  g_S [(size_t)T_STEPS * H_DIM];    //  8.0 MB
__device__ __half g_Whh[(size_t)H3 * H_DIM];        // 25.2 MB fp16 copy of W_hh
__device__ float  g_s0[H_DIM];
__device__ float  g_s1[H_DIM];
__device__ unsigned g_count;                        // monotonic barrier counter

// ---------------- helpers ----------------
__device__ __forceinline__ float sigmoidf_(float x) { return 1.0f / (1.0f + expf(-x)); }
__device__ __forceinline__ float eluf_(float x)     { return x > 0.0f ? x : expm1f(x); }
__device__ __forceinline__ float softplusf_(float x){ return fmaxf(x, 0.0f) + log1pf(expf(-fabsf(x))); }

__device__ __forceinline__ float warp_sum(float v) {
    #pragma unroll
    for (int o = 16; o > 0; o >>= 1) v += __shfl_xor_sync(0xFFFFFFFFu, v, o);
    return v;
}

// Single-counter monotonic grid barrier. Release: total arrivals >= NBLK*epoch.
// Arrival k+1 by any CTA is only possible after it passed barrier k, so
// count >= NBLK*k implies all NBLK CTAs arrived k times (induction on k).
__device__ __forceinline__ void grid_barrier(unsigned target) {
    __syncthreads();
    if (threadIdx.x == 0) {
        __threadfence();
        atomicAdd(&g_count, 1u);
        while (*(volatile unsigned*)&g_count < target) { }
        __threadfence();
    }
    __syncthreads();
}

// ---------------- kernel 0a: reset barrier state (graph-replay safety) ----
__global__ void reset_kernel() {
    if (threadIdx.x == 0) g_count = 0u;
}

// ---------------- kernel 0b: W_hh fp32 -> fp16 ----------------
__global__ void conv_whh_kernel(const float* __restrict__ W_hh) {
    size_t i = ((size_t)blockIdx.x * blockDim.x + threadIdx.x);   // float4 index
    float4 v = __ldg((const float4*)W_hh + i);
    __half2 h0 = __floats2half2_rn(v.x, v.y);
    __half2 h1 = __floats2half2_rn(v.z, v.w);
    uint2 o;
    o.x = *(unsigned*)&h0;
    o.y = *(unsigned*)&h1;
    ((uint2*)g_Whh)[i] = o;
}

// ---------------- kernel 1: GI = actions @ W_ih^T + b_ih ----------------
#define GI_TB 64
__global__ void __launch_bounds__(256) gi_kernel(
    const float* __restrict__ actions,
    const float* __restrict__ W_ih,
    const float* __restrict__ b_ih)
{
    __shared__ float act[GI_TB][A_DIM];    // 16 KB
    const int t0 = blockIdx.y * GI_TB;
    const int g  = blockIdx.x * 256 + threadIdx.x;

    for (int idx = threadIdx.x; idx < GI_TB * A_DIM / 4; idx += 256)
        ((float4*)&act[0][0])[idx] = ((const float4*)(actions + (size_t)t0 * A_DIM))[idx];
    __syncthreads();

    const float4* w = (const float4*)(W_ih + (size_t)g * A_DIM);
    float4 wreg[A_DIM / 4];
    #pragma unroll
    for (int i = 0; i < A_DIM / 4; i++) wreg[i] = __ldg(w + i);
    const float b = __ldg(b_ih + g);

    for (int tt = 0; tt < GI_TB; tt++) {
        float acc = b;
        #pragma unroll
        for (int i = 0; i < A_DIM / 4; i++) {
            float4 a = ((const float4*)act[tt])[i];
            acc += wreg[i].x*a.x + wreg[i].y*a.y + wreg[i].z*a.z + wreg[i].w*a.w;
        }
        g_GI[(size_t)(t0 + tt) * H3 + g] = acc;
    }
}

// ---------------- kernel 2: persistent sequential scan (split-K) ----------
// 32 warps/CTA; output j is owned by warp pair (wj, wj+16): each computes a
// 1024-element half-dot, partials combined through SMEM.
// Phase1: W_hh fp16 from L2 (25 MB/step, L2-resident).
// Phase2/3: fc1/fc2 rows fp16 resident in SMEM (128 KB/CTA, loaded once).
__global__ void __launch_bounds__(NTHR, 1) scan_kernel(
    const float* __restrict__ state,
    const float* __restrict__ b_hh,
    const float* __restrict__ fc1_w, const float* __restrict__ fc1_b,
    const float* __restrict__ fc2_w, const float* __restrict__ fc2_b)
{
    extern __shared__ char smem[];
    float*  sv   = (float*)smem;                       // 2048 fp32
    __half* fc1s = (__half*)(smem + 8192);             // JPB x 2048 half
    __half* fc2s = fc1s + JPB * H_DIM;                 // JPB x 2048 half
    float*  part = (float*)(fc2s + JPB * H_DIM);       // [3][32] partials

    const int tid  = threadIdx.x;
    const int warp = tid >> 5;
    const int lane = tid & 31;
    const int wj   = warp & 15;                        // output slot within CTA
    const int half = warp >> 4;                        // which K-half this warp does
    const int j    = blockIdx.x * JPB + wj;            // output element 0..2047
    const bool combiner = (half == 0) && (lane == 0);

    // ---- prologue: convert this CTA's fc rows to fp16 in SMEM ----
    {
        const int jbase = blockIdx.x * JPB;
        for (int idx = tid; idx < JPB * H_DIM; idx += NTHR) {
            int r = idx >> 11, c = idx & (H_DIM - 1);
            fc1s[idx] = __float2half_rn(fc1_w[(size_t)(jbase + r) * H_DIM + c]);
            fc2s[idx] = __float2half_rn(fc2_w[(size_t)(jbase + r) * H_DIM + c]);
        }
    }

    const __half* wr = g_Whh + (size_t)j * H_DIM;
    const __half* wz = g_Whh + (size_t)(H_DIM + j) * H_DIM;
    const __half* wn = g_Whh + (size_t)(2 * H_DIM + j) * H_DIM;
    const __half* w1 = fc1s + wj * H_DIM;
    const __half* w2 = fc2s + wj * H_DIM;

    const float bh_r = __ldg(b_hh + j);
    const float bh_z = __ldg(b_hh + H_DIM + j);
    const float bh_n = __ldg(b_hh + 2 * H_DIM + j);
    const float b1   = __ldg(fc1_b + j);
    const float b2   = __ldg(fc2_b + j);

    const int ibase = half * (H_DIM / 8);              // float4-unit offset: 0 or 256

    __syncthreads();   // fc SMEM ready (intra-CTA only)

    unsigned target = 0;
    for (int t = 0; t < T_STEPS; t++) {
        // ============ phase 1: GRU cell ============
        const float4* prev4 = (t == 0) ? (const float4*)state
                                       : (const float4*)(g_S + (size_t)(t - 1) * H_DIM);
        if (tid < H_DIM / 4)
            ((float4*)sv)[tid] = __ldcg(prev4 + tid);
        float gir = 0.f, giz = 0.f, gin = 0.f;
        if (combiner) {
            const float* gi = g_GI + (size_t)t * H3;
            gir = __ldg(gi + j);
            giz = __ldg(gi + H_DIM + j);
            gin = __ldg(gi + 2 * H_DIM + j);
        }
        __syncthreads();

        float ar = 0.f, az = 0.f, an = 0.f;
        #pragma unroll
        for (int ii = 0; ii < 8; ii++) {
            int i = ibase + lane + ii * 32;               // unit: 4 elements
            float4 h4 = ((const float4*)sv)[i];
            uint2 wa = __ldg((const uint2*)wr + i);
            uint2 wb = __ldg((const uint2*)wz + i);
            uint2 wc = __ldg((const uint2*)wn + i);
            float2 a0 = __half22float2(*(__half2*)&wa.x);
            float2 a1 = __half22float2(*(__half2*)&wa.y);
            float2 b0 = __half22float2(*(__half2*)&wb.x);
            float2 b1v= __half22float2(*(__half2*)&wb.y);
            float2 c0 = __half22float2(*(__half2*)&wc.x);
            float2 c1 = __half22float2(*(__half2*)&wc.y);
            ar += a0.x*h4.x + a0.y*h4.y + a1.x*h4.z + a1.y*h4.w;
            az += b0.x*h4.x + b0.y*h4.y + b1v.x*h4.z + b1v.y*h4.w;
            an += c0.x*h4.x + c0.y*h4.y + c1.x*h4.z + c1.y*h4.w;
        }
        ar = warp_sum(ar); az = warp_sum(az); an = warp_sum(an);
        if (lane == 0) {
            part[warp]      = ar;
            part[32 + warp] = az;
            part[64 + warp] = an;
        }
        __syncthreads();

        if (combiner) {
            float arT = part[wj]      + part[wj + 16];
            float azT = part[32 + wj] + part[32 + wj + 16];
            float anT = part[64 + wj] + part[64 + wj + 16];
            float r = sigmoidf_(gir + arT + bh_r);
            float z = sigmoidf_(giz + azT + bh_z);
            float n = tanhf   (gin + r * (anT + bh_n));
            float hnew = (1.0f - z) * n + z * sv[j];
            __stcg(&g_s0[j], eluf_(hnew));
        }
        target += NBLK; grid_barrier(target);

        // ============ phase 2: s1 = elu(s0 @ fc1^T + b1) ============
        if (tid < H_DIM / 4)
            ((float4*)sv)[tid] = __ldcg((const float4*)g_s0 + tid);
        __syncthreads();
        float acc1 = 0.f;
        #pragma unroll
        for (int ii = 0; ii < 8; ii++) {
            int i = ibase + lane + ii * 32;
            float4 h4 = ((const float4*)sv)[i];
            uint2 wv = ((const uint2*)w1)[i];
            float2 p0 = __half22float2(*(__half2*)&wv.x);
            float2 p1 = __half22float2(*(__half2*)&wv.y);
            acc1 += p0.x*h4.x + p0.y*h4.y + p1.x*h4.z + p1.y*h4.w;
        }
        acc1 = warp_sum(acc1);
        if (lane == 0) part[warp] = acc1;
        __syncthreads();
        if (combiner)
            __stcg(&g_s1[j], eluf_(part[wj] + part[wj + 16] + b1));
        target += NBLK; grid_barrier(target);

        // ============ phase 3: s2 = elu(s1 @ fc2^T + b2) ============
        if (tid < H_DIM / 4)
            ((float4*)sv)[tid] = __ldcg((const float4*)g_s1 + tid);
        __syncthreads();
        float acc2 = 0.f;
        #pragma unroll
        for (int ii = 0; ii < 8; ii++) {
            int i = ibase + lane + ii * 32;
            float4 h4 = ((const float4*)sv)[i];
            uint2 wv = ((const uint2*)w2)[i];
            float2 p0 = __half22float2(*(__half2*)&wv.x);
            float2 p1 = __half22float2(*(__half2*)&wv.y);
            acc2 += p0.x*h4.x + p0.y*h4.y + p1.x*h4.z + p1.y*h4.w;
        }
        acc2 = warp_sum(acc2);
        if (lane == 0) part[warp] = acc2;
        __syncthreads();
        if (combiner)
            __stcg(&g_S[(size_t)t * H_DIM + j], eluf_(part[wj] + part[wj + 16] + b2));
        target += NBLK; grid_barrier(target);
    }
}

// ---------------- kernel 3: heads — out = S @ W^T + b (softplus for std) ----
__global__ void __launch_bounds__(256) head_gemm(
    const float* __restrict__ mean_w, const float* __restrict__ mean_b,
    const float* __restrict__ std_w,  const float* __restrict__ std_b,
    float* __restrict__ out)
{
    const float* Wmat = blockIdx.z ? std_w : mean_w;
    const float* bias = blockIdx.z ? std_b : mean_b;
    const int m0 = blockIdx.y * 128;
    const int n0 = blockIdx.x * 128;

    __shared__ float As[8][128];
    __shared__ float Bs[8][128];

    const int tid  = threadIdx.x;
    const int lrow = tid >> 1;
    const int lcol = (tid & 1) * 4;
    const int tx   = tid & 15;
    const int ty   = tid >> 4;

    float acc[8][8];
    #pragma unroll
    for (int i = 0; i < 8; i++)
        #pragma unroll
        for (int jj = 0; jj < 8; jj++) acc[i][jj] = 0.f;

    const float* aptr = g_S  + (size_t)(m0 + lrow) * H_DIM + lcol;
    const float* bptr = Wmat + (size_t)(n0 + lrow) * H_DIM + lcol;

    for (int k0 = 0; k0 < H_DIM; k0 += 8) {
        float4 a4 = *(const float4*)(aptr + k0);
        float4 b4 = *(const float4*)(bptr + k0);
        __syncthreads();
        As[lcol+0][lrow] = a4.x; As[lcol+1][lrow] = a4.y;
        As[lcol+2][lrow] = a4.z; As[lcol+3][lrow] = a4.w;
        Bs[lcol+0][lrow] = b4.x; Bs[lcol+1][lrow] = b4.y;
        Bs[lcol+2][lrow] = b4.z; Bs[lcol+3][lrow] = b4.w;
        __syncthreads();
        #pragma unroll
        for (int kk = 0; kk < 8; kk++) {
            float a[8], b[8];
            *(float4*)&a[0] = *(const float4*)&As[kk][ty * 4];
            *(float4*)&a[4] = *(const float4*)&As[kk][ty * 4 + 64];
            *(float4*)&b[0] = *(const float4*)&Bs[kk][tx * 4];
            *(float4*)&b[4] = *(const float4*)&Bs[kk][tx * 4 + 64];
            #pragma unroll
            for (int i = 0; i < 8; i++)
                #pragma unroll
                for (int jj = 0; jj < 8; jj++)
                    acc[i][jj] += a[i] * b[jj];
        }
    }

    const size_t zoff = (size_t)blockIdx.z * T_STEPS * H_DIM;
    #pragma unroll
    for (int i = 0; i < 8; i++) {
        int m = m0 + ty * 4 + (i & 3) + (i >> 2) * 64;
        #pragma unroll
        for (int jj = 0; jj < 8; jj++) {
            int n = n0 + tx * 4 + (jj & 3) + (jj >> 2) * 64;
            float v = acc[i][jj] + bias[n];
            if (blockIdx.z) v = softplusf_(v);
            out[zoff + (size_t)m * H_DIM + n] = v;
        }
    }
}

// ---------------- launch ----------------
extern "C" void kernel_launch(void* const* d_in, const int* in_sizes, int n_in,
                              void* d_out, int out_size) {
    const float* actions = (const float*)d_in[0];
    const float* state   = (const float*)d_in[1];
    const float* W_ih    = (const float*)d_in[2];
    const float* W_hh    = (const float*)d_in[3];
    const float* b_ih    = (const float*)d_in[4];
    const float* b_hh    = (const float*)d_in[5];
    const float* fc1_w   = (const float*)d_in[6];
    const float* fc1_b   = (const float*)d_in[7];
    const float* fc2_w   = (const float*)d_in[8];
    const float* fc2_b   = (const float*)d_in[9];
    const float* mean_w  = (const float*)d_in[10];
    const float* mean_b  = (const float*)d_in[11];
    const float* std_w   = (const float*)d_in[12];
    const float* std_b   = (const float*)d_in[13];
    float* out = (float*)d_out;

    static bool attr_set = false;
    if (!attr_set) {
        cudaFuncSetAttribute(scan_kernel,
                             cudaFuncAttributeMaxDynamicSharedMemorySize, SMEM_BYTES);
        attr_set = true;
    }

    reset_kernel<<<1, 32>>>();
    conv_whh_kernel<<<(H3 * H_DIM / 4) / 256, 256>>>(W_hh);
    gi_kernel<<<dim3(H3 / 256, T_STEPS / GI_TB), 256>>>(actions, W_ih, b_ih);
    scan_kernel<<<NBLK, NTHR, SMEM_BYTES>>>(state, b_hh, fc1_w, fc1_b, fc2_w, fc2_b);
    head_gemm<<<dim3(H_DIM / 128, T_STEPS / 128, 2), 256>>>(mean_w, mean_b, std_w, std_b, out);
}

// round 14
// speedup vs baseline: 1.3011x; 1.3011x over previous
#include <cuda_runtime.h>
#include <cuda_fp16.h>
#include <cstdint>

#define T_STEPS 1024
#define A_DIM   64
#define H_DIM   2048
#define H3      (3 * H_DIM)
#define NBLK    128
#define NTHR    512            // 16 warps -> 128*16 = 2048 warps, 1 output/warp
#define JPB     16             // outputs per CTA
#define SMEM_BYTES (8192 + 2 * JPB * H_DIM * 2)   // sv(fp32) + fc1 + fc2 (half) = 139264

// ---------------- scratch (static device allocs: allowed) ----------------
__device__ float  g_GI[(size_t)T_STEPS * H3];       // 25.2 MB
__device__ float  g_S [(size_t)T_STEPS * H_DIM];    //  8.0 MB
__device__ __half g_Whh[(size_t)H3 * H_DIM];        // 25.2 MB fp16 copy of W_hh
__device__ float  g_s0[H_DIM];
__device__ float  g_s1[H_DIM];
__device__ unsigned g_count;                        // monotonic barrier counter

// ---------------- helpers ----------------
__device__ __forceinline__ float sigmoidf_(float x) { return 1.0f / (1.0f + expf(-x)); }
__device__ __forceinline__ float eluf_(float x)     { return x > 0.0f ? x : expm1f(x); }
__device__ __forceinline__ float softplusf_(float x){ return fmaxf(x, 0.0f) + log1pf(expf(-fabsf(x))); }

__device__ __forceinline__ float warp_sum(float v) {
    #pragma unroll
    for (int o = 16; o > 0; o >>= 1) v += __shfl_xor_sync(0xFFFFFFFFu, v, o);
    return v;
}

// 8-halfs fp16 dot against 8 fp32 values (two float4), fp32 accumulate.
__device__ __forceinline__ float dot8(uint4 w, float4 h0, float4 h1) {
    float2 p0 = __half22float2(*(__half2*)&w.x);
    float2 p1 = __half22float2(*(__half2*)&w.y);
    float2 p2 = __half22float2(*(__half2*)&w.z);
    float2 p3 = __half22float2(*(__half2*)&w.w);
    return p0.x*h0.x + p0.y*h0.y + p1.x*h0.z + p1.y*h0.w
         + p2.x*h1.x + p2.y*h1.y + p3.x*h1.z + p3.y*h1.w;
}

// Single-counter monotonic grid barrier with backoff. Release condition:
// total arrivals >= NBLK*epoch. Arrival k+1 by any CTA is only possible after
// it passed barrier k, so count >= NBLK*k implies all CTAs arrived k times.
// Correctness of this barrier was validated in R13 (rel_err == fp32-path value).
__device__ __forceinline__ void grid_barrier(unsigned target) {
    __syncthreads();
    if (threadIdx.x == 0) {
        __threadfence();
        atomicAdd(&g_count, 1u);
        unsigned v;
        for (;;) {
            asm volatile("ld.global.cv.u32 %0, [%1];" : "=r"(v) : "l"(&g_count));
            if (v >= target) break;
            __nanosleep(64);           // bound poll traffic on the hot line
        }
        __threadfence();
    }
    __syncthreads();
}

// ---------------- kernel 0a: reset barrier state (graph-replay safety) ----
__global__ void reset_kernel() {
    if (threadIdx.x == 0) g_count = 0u;
}

// ---------------- kernel 0b: W_hh fp32 -> fp16 ----------------
__global__ void conv_whh_kernel(const float* __restrict__ W_hh) {
    size_t i = ((size_t)blockIdx.x * blockDim.x + threadIdx.x);   // float4 index
    float4 v = __ldg((const float4*)W_hh + i);
    __half2 h0 = __floats2half2_rn(v.x, v.y);
    __half2 h1 = __floats2half2_rn(v.z, v.w);
    uint2 o;
    o.x = *(unsigned*)&h0;
    o.y = *(unsigned*)&h1;
    ((uint2*)g_Whh)[i] = o;
}

// ---------------- kernel 1: GI = actions @ W_ih^T + b_ih ----------------
#define GI_TB 64
__global__ void __launch_bounds__(256) gi_kernel(
    const float* __restrict__ actions,
    const float* __restrict__ W_ih,
    const float* __restrict__ b_ih)
{
    __shared__ float act[GI_TB][A_DIM];    // 16 KB
    const int t0 = blockIdx.y * GI_TB;
    const int g  = blockIdx.x * 256 + threadIdx.x;

    for (int idx = threadIdx.x; idx < GI_TB * A_DIM / 4; idx += 256)
        ((float4*)&act[0][0])[idx] = ((const float4*)(actions + (size_t)t0 * A_DIM))[idx];
    __syncthreads();

    const float4* w = (const float4*)(W_ih + (size_t)g * A_DIM);
    float4 wreg[A_DIM / 4];
    #pragma unroll
    for (int i = 0; i < A_DIM / 4; i++) wreg[i] = __ldg(w + i);
    const float b = __ldg(b_ih + g);

    for (int tt = 0; tt < GI_TB; tt++) {
        float acc = b;
        #pragma unroll
        for (int i = 0; i < A_DIM / 4; i++) {
            float4 a = ((const float4*)act[tt])[i];
            acc += wreg[i].x*a.x + wreg[i].y*a.y + wreg[i].z*a.z + wreg[i].w*a.w;
        }
        g_GI[(size_t)(t0 + tt) * H3 + g] = acc;
    }
}

// ---------------- kernel 2: persistent sequential scan ----------------
// 512 threads (reg budget 128 -> no spills). One warp owns one output j.
// Phase1: W_hh fp16 streamed from L2 (25 MB/step, L2-resident), uint4 loads.
// Phase2/3: fc1/fc2 rows fp16 resident in SMEM (128 KB/CTA, loaded once).
__global__ void __launch_bounds__(NTHR, 1) scan_kernel(
    const float* __restrict__ state,
    const float* __restrict__ b_hh,
    const float* __restrict__ fc1_w, const float* __restrict__ fc1_b,
    const float* __restrict__ fc2_w, const float* __restrict__ fc2_b)
{
    extern __shared__ char smem[];
    float*  sv   = (float*)smem;                       // 2048 fp32
    __half* fc1s = (__half*)(smem + 8192);             // JPB x 2048 half
    __half* fc2s = fc1s + JPB * H_DIM;                 // JPB x 2048 half

    const int tid  = threadIdx.x;
    const int warp = tid >> 5;
    const int lane = tid & 31;
    const int j    = blockIdx.x * JPB + warp;          // output element 0..2047

    // ---- prologue: convert this CTA's fc rows to fp16 in SMEM ----
    {
        const int jbase = blockIdx.x * JPB;
        for (int idx = tid; idx < JPB * H_DIM; idx += NTHR) {
            int r = idx >> 11, c = idx & (H_DIM - 1);
            fc1s[idx] = __float2half_rn(fc1_w[(size_t)(jbase + r) * H_DIM + c]);
            fc2s[idx] = __float2half_rn(fc2_w[(size_t)(jbase + r) * H_DIM + c]);
        }
    }

    const uint4* wr = (const uint4*)(g_Whh + (size_t)j * H_DIM);
    const uint4* wz = (const uint4*)(g_Whh + (size_t)(H_DIM + j) * H_DIM);
    const uint4* wn = (const uint4*)(g_Whh + (size_t)(2 * H_DIM + j) * H_DIM);
    const uint4* w1 = (const uint4*)(fc1s + warp * H_DIM);
    const uint4* w2 = (const uint4*)(fc2s + warp * H_DIM);

    const float bh_r = __ldg(b_hh + j);
    const float bh_z = __ldg(b_hh + H_DIM + j);
    const float bh_n = __ldg(b_hh + 2 * H_DIM + j);
    const float b1   = __ldg(fc1_b + j);
    const float b2   = __ldg(fc2_b + j);

    __syncthreads();   // fc SMEM ready (intra-CTA only)

    unsigned target = 0;
    for (int t = 0; t < T_STEPS; t++) {
        // ============ phase 1: GRU cell ============
        const float4* prev4 = (t == 0) ? (const float4*)state
                                       : (const float4*)(g_S + (size_t)(t - 1) * H_DIM);
        float4 pv = __ldcg(prev4 + tid);
        float gir = 0.f, giz = 0.f, gin = 0.f;
        if (lane == 0) {
            const float* gi = g_GI + (size_t)t * H3;
            gir = __ldg(gi + j);
            giz = __ldg(gi + H_DIM + j);
            gin = __ldg(gi + 2 * H_DIM + j);
        }
        ((float4*)sv)[tid] = pv;
        __syncthreads();

        float ar = 0.f, az = 0.f, an = 0.f;
        #pragma unroll 4
        for (int ii = 0; ii < 8; ii++) {
            int i = lane + ii * 32;                       // uint4 unit: 8 halfs
            float4 h0 = ((const float4*)sv)[2 * i];
            float4 h1 = ((const float4*)sv)[2 * i + 1];
            uint4 wa = __ldg(wr + i);
            uint4 wb = __ldg(wz + i);
            uint4 wc = __ldg(wn + i);
            ar += dot8(wa, h0, h1);
            az += dot8(wb, h0, h1);
            an += dot8(wc, h0, h1);
        }
        ar = warp_sum(ar); az = warp_sum(az); an = warp_sum(an);

        if (lane == 0) {
            float r = sigmoidf_(gir + ar + bh_r);
            float z = sigmoidf_(giz + az + bh_z);
            float n = tanhf   (gin + r * (an + bh_n));
            float hnew = (1.0f - z) * n + z * sv[j];
            __stcg(&g_s0[j], eluf_(hnew));
        }
        target += NBLK; grid_barrier(target);

        // ============ phase 2: s1 = elu(s0 @ fc1^T + b1) ============
        ((float4*)sv)[tid] = __ldcg((const float4*)g_s0 + tid);
        __syncthreads();
        float acc1 = 0.f;
        #pragma unroll
        for (int ii = 0; ii < 8; ii++) {
            int i = lane + ii * 32;
            float4 h0 = ((const float4*)sv)[2 * i];
            float4 h1 = ((const float4*)sv)[2 * i + 1];
            acc1 += dot8(w1[i], h0, h1);
        }
        acc1 = warp_sum(acc1);
        if (lane == 0) __stcg(&g_s1[j], eluf_(acc1 + b1));
        target += NBLK; grid_barrier(target);

        // ============ phase 3: s2 = elu(s1 @ fc2^T + b2) ============
        ((float4*)sv)[tid] = __ldcg((const float4*)g_s1 + tid);
        __syncthreads();
        float acc2 = 0.f;
        #pragma unroll
        for (int ii = 0; ii < 8; ii++) {
            int i = lane + ii * 32;
            float4 h0 = ((const float4*)sv)[2 * i];
            float4 h1 = ((const float4*)sv)[2 * i + 1];
            acc2 += dot8(w2[i], h0, h1);
        }
        acc2 = warp_sum(acc2);
        if (lane == 0) __stcg(&g_S[(size_t)t * H_DIM + j], eluf_(acc2 + b2));
        target += NBLK; grid_barrier(target);
    }
}

// ---------------- kernel 3: heads — out = S @ W^T + b (softplus for std) ----
__global__ void __launch_bounds__(256) head_gemm(
    const float* __restrict__ mean_w, const float* __restrict__ mean_b,
    const float* __restrict__ std_w,  const float* __restrict__ std_b,
    float* __restrict__ out)
{
    const float* Wmat = blockIdx.z ? std_w : mean_w;
    const float* bias = blockIdx.z ? std_b : mean_b;
    const int m0 = blockIdx.y * 128;
    const int n0 = blockIdx.x * 128;

    __shared__ float As[8][128];
    __shared__ float Bs[8][128];

    const int tid  = threadIdx.x;
    const int lrow = tid >> 1;
    const int lcol = (tid & 1) * 4;
    const int tx   = tid & 15;
    const int ty   = tid >> 4;

    float acc[8][8];
    #pragma unroll
    for (int i = 0; i < 8; i++)
        #pragma unroll
        for (int jj = 0; jj < 8; jj++) acc[i][jj] = 0.f;

    const float* aptr = g_S  + (size_t)(m0 + lrow) * H_DIM + lcol;
    const float* bptr = Wmat + (size_t)(n0 + lrow) * H_DIM + lcol;

    for (int k0 = 0; k0 < H_DIM; k0 += 8) {
        float4 a4 = *(const float4*)(aptr + k0);
        float4 b4 = *(const float4*)(bptr + k0);
        __syncthreads();
        As[lcol+0][lrow] = a4.x; As[lcol+1][lrow] = a4.y;
        As[lcol+2][lrow] = a4.z; As[lcol+3][lrow] = a4.w;
        Bs[lcol+0][lrow] = b4.x; Bs[lcol+1][lrow] = b4.y;
        Bs[lcol+2][lrow] = b4.z; Bs[lcol+3][lrow] = b4.w;
        __syncthreads();
        #pragma unroll
        for (int kk = 0; kk < 8; kk++) {
            float a[8], b[8];
            *(float4*)&a[0] = *(const float4*)&As[kk][ty * 4];
            *(float4*)&a[4] = *(const float4*)&As[kk][ty * 4 + 64];
            *(float4*)&b[0] = *(const float4*)&Bs[kk][tx * 4];
            *(float4*)&b[4] = *(const float4*)&Bs[kk][tx * 4 + 64];
            #pragma unroll
            for (int i = 0; i < 8; i++)
                #pragma unroll
                for (int jj = 0; jj < 8; jj++)
                    acc[i][jj] += a[i] * b[jj];
        }
    }

    const size_t zoff = (size_t)blockIdx.z * T_STEPS * H_DIM;
    #pragma unroll
    for (int i = 0; i < 8; i++) {
        int m = m0 + ty * 4 + (i & 3) + (i >> 2) * 64;
        #pragma unroll
        for (int jj = 0; jj < 8; jj++) {
            int n = n0 + tx * 4 + (jj & 3) + (jj >> 2) * 64;
            float v = acc[i][jj] + bias[n];
            if (blockIdx.z) v = softplusf_(v);
            out[zoff + (size_t)m * H_DIM + n] = v;
        }
    }
}

// ---------------- launch ----------------
extern "C" void kernel_launch(void* const* d_in, const int* in_sizes, int n_in,
                              void* d_out, int out_size) {
    const float* actions = (const float*)d_in[0];
    const float* state   = (const float*)d_in[1];
    const float* W_ih    = (const float*)d_in[2];
    const float* W_hh    = (const float*)d_in[3];
    const float* b_ih    = (const float*)d_in[4];
    const float* b_hh    = (const float*)d_in[5];
    const float* fc1_w   = (const float*)d_in[6];
    const float* fc1_b   = (const float*)d_in[7];
    const float* fc2_w   = (const float*)d_in[8];
    const float* fc2_b   = (const float*)d_in[9];
    const float* mean_w  = (const float*)d_in[10];
    const float* mean_b  = (const float*)d_in[11];
    const float* std_w   = (const float*)d_in[12];
    const float* std_b   = (const float*)d_in[13];
    float* out = (float*)d_out;

    static bool attr_set = false;
    if (!attr_set) {
        cudaFuncSetAttribute(scan_kernel,
                             cudaFuncAttributeMaxDynamicSharedMemorySize, SMEM_BYTES);
        attr_set = true;
    }

    reset_kernel<<<1, 32>>>();
    conv_whh_kernel<<<(H3 * H_DIM / 4) / 256, 256>>>(W_hh);
    gi_kernel<<<dim3(H3 / 256, T_STEPS / GI_TB), 256>>>(actions, W_ih, b_ih);
    scan_kernel<<<NBLK, NTHR, SMEM_BYTES>>>(state, b_hh, fc1_w, fc1_b, fc2_w, fc2_b);
    head_gemm<<<dim3(H_DIM / 128, T_STEPS / 128, 2), 256>>>(mean_w, mean_b, std_w, std_b, out);
}